// round 12
// baseline (speedup 1.0000x reference)
#include <cuda_runtime.h>

// EffectiveProbability: post = normalize(p * (CM @ c)) per pixel.
// Input row-normalizations cancel against the output normalization -> skipped.
//
// prior/current [8,21,512,512] f32, cm [21,21] f32, out [B*H*W,21] f32.
//
// R12: software-pipelined grid-stride version of R11.
//  - Each thread handles ~8 pixels. Per iteration it issues the NEXT pixel's
//    cv loads (double-buffered cvA/cvB) and the CURRENT pixel's pv loads
//    before the 441-FFMA block, so ~42 LDGs stay in flight during compute
//    (R11's loads were bursty: idle DRAM during each compute phase).
//  - pv is consumed only in the epilogue (s_i computed first), giving its
//    loads the full FFMA window of latency cover.
//  - CM in __constant__ (uniform-port LDCU), __ldcs/__stcs streaming hints,
//    float4 smem-staged coalesced flush: all carried from R9/R11.

#define NCLS 21
#define HWSHIFT 18              // H*W = 512*512 = 2^18
#define HWSZ (1 << HWSHIFT)
#define BLOCK 256
#define GRID 1024               // 2^21 / (1024*256) = 8 pixels per thread

__constant__ float c_cm[NCLS * NCLS];

__device__ __forceinline__ size_t pix_base(int n) {
    const int b  = n >> HWSHIFT;
    const int hw = n & (HWSZ - 1);
    return ((size_t)b * NCLS << HWSHIFT) + hw;
}

__device__ __forceinline__ void load21(float (&dst)[NCLS], const float* __restrict__ p) {
    #pragma unroll
    for (int j = 0; j < NCLS; j++) dst[j] = __ldcs(p + ((size_t)j << HWSHIFT));
}

// One pipeline stage: prefetch pv(current)+cv(next), compute, stage, flush.
__device__ __forceinline__ void do_iter(
    float (&cv)[NCLS], float (&cvn)[NCLS],
    const float* __restrict__ prior, const float* __restrict__ current,
    float* __restrict__ out, float* __restrict__ s_out,
    int n, int it, int niter, int stride, int npix, int tid)
{
    const bool act = (n < npix);

    // Issue current pixel's prior loads now; consumed only in the epilogue,
    // so the FFMA block below covers their latency.
    float pv[NCLS];
    if (act) load21(pv, prior + pix_base(n));

    // Issue next pixel's cv loads into the other buffer (covers next iter).
    const int n2 = n + stride;
    if (it + 1 < niter && n2 < npix) load21(cvn, current + pix_base(n2));

    float inv = 0.0f;
    float post[NCLS];
    if (act) {
        // s_i = CM[i,:] . cv   (LDCU on uniform port + FFMA only)
        #pragma unroll
        for (int i = 0; i < NCLS; i++) {
            float s = 0.0f;
            #pragma unroll
            for (int j = 0; j < NCLS; j++)
                s = fmaf(c_cm[i * NCLS + j], cv[j], s);
            post[i] = s;
        }
        // Epilogue: first use of pv -> its loads had the whole FFMA block.
        float acc = 0.0f;
        #pragma unroll
        for (int i = 0; i < NCLS; i++) {
            const float t = pv[i] * post[i];
            post[i] = t;
            acc += t;
        }
        inv = 1.0f / acc;
        #pragma unroll
        for (int i = 0; i < NCLS; i++)
            s_out[tid * NCLS + i] = post[i] * inv;   // stride 21: conflict-free
    }
    __syncthreads();

    // Flush this iteration's [BLOCK,21] tile; fully coalesced float4 stream.
    const int    tile0   = n - tid;                  // first pixel of the tile
    const int    valid   = min(BLOCK, npix - tile0);
    const size_t out_off = (size_t)tile0 * NCLS;
    if (valid == BLOCK) {
        float4*       o4 = (float4*)(out + out_off);
        const float4* s4 = (const float4*)s_out;
        #pragma unroll
        for (int k = tid; k < BLOCK * NCLS / 4; k += BLOCK)
            __stcs(o4 + k, s4[k]);
    } else if (valid > 0) {
        const int count = valid * NCLS;
        for (int k = tid; k < count; k += BLOCK)
            __stcs(out + out_off + k, s_out[k]);
    }
    __syncthreads();                                 // s_out reused next iter
}

__global__ __launch_bounds__(BLOCK, 2)
void eff_prob_kernel(const float* __restrict__ prior,
                     const float* __restrict__ current,
                     float* __restrict__ out,
                     int npix)
{
    __shared__ float s_out[BLOCK * NCLS];            // 21504 B

    const int tid    = threadIdx.x;
    const int stride = gridDim.x * BLOCK;
    const int niter  = (npix + stride - 1) / stride; // uniform across grid

    int n = blockIdx.x * BLOCK + tid;

    float cvA[NCLS], cvB[NCLS];
    if (n < npix) load21(cvA, current + pix_base(n));   // prologue fill

    for (int it = 0; it < niter; it += 2) {
        do_iter(cvA, cvB, prior, current, out, s_out,
                n,          it,     niter, stride, npix, tid);
        if (it + 1 < niter)
            do_iter(cvB, cvA, prior, current, out, s_out,
                    n + stride, it + 1, niter, stride, npix, tid);
        n += 2 * stride;
    }
}

extern "C" void kernel_launch(void* const* d_in, const int* in_sizes, int n_in,
                              void* d_out, int out_size)
{
    const float* prior   = (const float*)d_in[0];
    const float* current = (const float*)d_in[1];
    const float* cm      = (const float*)d_in[2];
    float*       out     = (float*)d_out;

    // D2D copy into the constant bank; async -> graph-capturable memcpy node.
    cudaMemcpyToSymbolAsync(c_cm, cm, NCLS * NCLS * sizeof(float), 0,
                            cudaMemcpyDeviceToDevice, 0);

    const int npix = in_sizes[0] / NCLS;   // B*H*W
    eff_prob_kernel<<<GRID, BLOCK>>>(prior, current, out, npix);
}

// round 13
// speedup vs baseline: 1.4446x; 1.4446x over previous
#include <cuda_runtime.h>

// EffectiveProbability: post = normalize(p * (CM @ c)) per pixel.
// Input row-normalizations cancel against the output normalization -> skipped.
//
// prior/current [8,21,512,512] f32, cm [21,21] f32, out [B*H*W,21] f32.
//
// R13: R11 (best: 84.8us total / 81.1us kernel, 76% DRAM — within ~2% of the
// 528MB traffic floor) with ONE knob: BLOCK 256 -> 128. Doubles resident
// blocks per SM (8 @ 58 regs) and quadruples grid-level phase interleave so
// the per-block load-burst / compute / flush phases from different blocks
// tile more densely at the LTS. All R9/R11 structure retained:
//  - CM in __constant__ -> uniform-port LDCU (no LSU/smem traffic)
//  - all 42 input loads front-batched, __ldcs streaming (single-touch)
//  - normalize in registers, smem-staged float4 __stcs coalesced flush.

#define NCLS 21
#define HWSHIFT 18              // H*W = 512*512 = 2^18
#define HWSZ (1 << HWSHIFT)
#define BLOCK 128

__constant__ float c_cm[NCLS * NCLS];

__global__ __launch_bounds__(BLOCK)
void eff_prob_kernel(const float* __restrict__ prior,
                     const float* __restrict__ current,
                     float* __restrict__ out,
                     int npix)
{
    __shared__ float s_out[BLOCK * NCLS];    // 10752 B, 16B-divisible

    const int tid = threadIdx.x;
    const int n = blockIdx.x * BLOCK + tid;
    if (n < npix) {
        const int b  = n >> HWSHIFT;
        const int hw = n & (HWSZ - 1);
        const size_t base = ((size_t)b * NCLS << HWSHIFT) + hw;
        const float* __restrict__ cp = current + base;
        const float* __restrict__ pp = prior + base;

        // Front-batched fully-coalesced streaming loads (single-touch data:
        // evict-first). Maximum MLP; no in-loop DRAM dependency.
        float cv[NCLS];
        #pragma unroll
        for (int j = 0; j < NCLS; j++) cv[j] = __ldcs(cp + ((size_t)j << HWSHIFT));
        float pv[NCLS];
        #pragma unroll
        for (int j = 0; j < NCLS; j++) pv[j] = __ldcs(pp + ((size_t)j << HWSHIFT));

        float post[NCLS];
        float acc = 0.0f;
        #pragma unroll
        for (int i = 0; i < NCLS; i++) {
            float s = 0.0f;
            #pragma unroll
            for (int j = 0; j < NCLS; j++)
                s = fmaf(c_cm[i * NCLS + j], cv[j], s);   // LDCU (uniform port) + FFMA
            const float t = pv[i] * s;
            post[i] = t;
            acc += t;
        }
        const float inv = 1.0f / acc;

        // Normalized values into smem staging.
        // Write stride 21 words across the warp: gcd(21,32)=1 -> conflict-free.
        #pragma unroll
        for (int i = 0; i < NCLS; i++)
            s_out[tid * NCLS + i] = post[i] * inv;
    }
    __syncthreads();

    // Vectorized flush: [BLOCK*21] floats = BLOCK*21/4 float4 groups.
    // Fully coalesced LDS.128 + STG.128, streaming stores.
    const int    valid   = min(BLOCK, npix - blockIdx.x * BLOCK);
    const size_t out_off = (size_t)blockIdx.x * BLOCK * NCLS;
    if (valid == BLOCK) {
        float4*       o4 = (float4*)(out + out_off);
        const float4* s4 = (const float4*)s_out;
        #pragma unroll
        for (int k = tid; k < BLOCK * NCLS / 4; k += BLOCK)
            __stcs(o4 + k, s4[k]);
    } else {
        // Tail (never taken for npix = 2^21): scalar flush.
        const int count = valid * NCLS;
        for (int k = tid; k < count; k += BLOCK)
            __stcs(out + out_off + k, s_out[k]);
    }
}

extern "C" void kernel_launch(void* const* d_in, const int* in_sizes, int n_in,
                              void* d_out, int out_size)
{
    const float* prior   = (const float*)d_in[0];
    const float* current = (const float*)d_in[1];
    const float* cm      = (const float*)d_in[2];
    float*       out     = (float*)d_out;

    // D2D copy into the constant bank; async -> graph-capturable memcpy node.
    cudaMemcpyToSymbolAsync(c_cm, cm, NCLS * NCLS * sizeof(float), 0,
                            cudaMemcpyDeviceToDevice, 0);

    const int npix = in_sizes[0] / NCLS;   // B*H*W
    const int grid = (npix + BLOCK - 1) / BLOCK;
    eff_prob_kernel<<<grid, BLOCK>>>(prior, current, out, npix);
}